// round 10
// baseline (speedup 1.0000x reference)
#include <cuda_runtime.h>
#include <math.h>
#include <stdint.h>

// Problem constants
#define N_IMG     16
#define N_CH      3
#define NSLICE    (N_IMG * N_CH)          // 48
#define BINS      64
#define SLICE_ELEMS (1024 * 1024)

#define HTHREADS  128
#define BPS       18                              // 864 blocks (one wave at occ 6)
#define NBLOCKS   (NSLICE * BPS)
// Two u16 counter arrays [64][128] = 16 KB each
#define HARR_U16  (BINS * HTHREADS)               // 8192 u16 per array
#define HSMEM_BYTES (2 * HARR_U16 * 2)            // 32 KB

// Params layout (in_ch,out_ch row-major), per reference
#define P_W1 0
#define P_B1 24576
#define P_W2 24704
#define P_B2 28800
#define P_G  28832

__device__ float g_part[NBLOCKS * BINS];

__global__ __launch_bounds__(HTHREADS, 6)
void hist_kernel(const float* __restrict__ img) {
    extern __shared__ unsigned short sh[];   // A = sh[0..8191], B = sh[8192..16383]
    const int tid = threadIdx.x;

    {
        uint4* z = reinterpret_cast<uint4*>(sh);
        #pragma unroll
        for (int i = tid; i < (2 * HARR_U16) / 8; i += HTHREADS)
            z[i] = make_uint4(0u, 0u, 0u, 0u);
    }
    __syncthreads();

    const int slice = blockIdx.x / BPS;
    const int chunk = blockIdx.x % BPS;
    const float4* base = reinterpret_cast<const float4*>(img + (size_t)slice * SLICE_ELEMS);
    const int n4   = SLICE_ELEMS / 4;                 // 262144
    const int per  = (n4 + BPS - 1) / BPS;            // 14564
    const int start = chunk * per;
    const int end   = min(start + per, n4);

    // Within-bin u16 index: (t&63)*2 + (t>>6) -> per-warp banks = lane (conflict-free).
    // Two threads sharing a 32-bit word are in different warps, disjoint halfwords.
    const int slot = ((tid & 63) << 1) + (tid >> 6);
    unsigned short* pA = sh + slot;                    // A[b] at pA[b*128]
    unsigned short* pB = sh + HARR_U16 + slot;         // B[b] at pB[b*128]

#define PROCPAIR(vA, vB) { \
        int ba = (int)__fmul_rd((vA), 64.0f); \
        int bb = (int)__fmul_rd((vB), 64.0f); \
        unsigned short ca = pA[ba * HTHREADS]; \
        unsigned short cb = pB[bb * HTHREADS]; \
        pA[ba * HTHREADS] = (unsigned short)(ca + 1); \
        pB[bb * HTHREADS] = (unsigned short)(cb + 1); }
#define PROC(v4) { PROCPAIR((v4).x, (v4).y); PROCPAIR((v4).z, (v4).w); }

    // Double-buffered, depth 4 (8 resident float4 = 32 regs -> no spill at occ 6).
    int i = start + tid;
    float4 A[4], B[4];
    bool hasA = (i + 3 * HTHREADS < end);
    if (hasA) {
        #pragma unroll
        for (int u = 0; u < 4; u++) A[u] = __ldcs(base + i + u * HTHREADS);
    }
    while (hasA) {
        const int j = i + 4 * HTHREADS;
        const bool hasB = (j + 3 * HTHREADS < end);
        if (hasB) {
            #pragma unroll
            for (int u = 0; u < 4; u++) B[u] = __ldcs(base + j + u * HTHREADS);
        }
        #pragma unroll
        for (int u = 0; u < 4; u++) PROC(A[u]);
        i = j;
        if (!hasB) break;
        const int k = j + 4 * HTHREADS;
        hasA = (k + 3 * HTHREADS < end);
        if (hasA) {
            #pragma unroll
            for (int u = 0; u < 4; u++) A[u] = __ldcs(base + k + u * HTHREADS);
        }
        #pragma unroll
        for (int u = 0; u < 4; u++) PROC(B[u]);
        i = k;
    }
    for (; i < end; i += HTHREADS) {
        float4 a = __ldcs(base + i);
        PROC(a);
    }
#undef PROC
#undef PROCPAIR
    __syncthreads();

    // Epilogue: arrays as u32 [64][64]; packed lo/hi sums < 2^16 each.
    const unsigned int* WA = reinterpret_cast<const unsigned int*>(sh);
    const unsigned int* WB = WA + (HARR_U16 / 2);
    const int wid  = tid >> 5;
    const int lane = tid & 31;
    #pragma unroll
    for (int r = 0; r < 16; r++) {
        const int b = wid * 16 + r;
        const unsigned int* ra = WA + b * 64;
        const unsigned int* rb = WB + b * 64;
        unsigned int s = ra[lane] + ra[lane + 32] + rb[lane] + rb[lane + 32];
        #pragma unroll
        for (int d = 16; d >= 1; d >>= 1)
            s += __shfl_down_sync(0xFFFFFFFFu, s, d);
        if (lane == 0)
            g_part[blockIdx.x * BINS + b] = (float)((s & 0xFFFFu) + (s >> 16));
    }
}

// MLP with PDL: grid=16 (one image per block), 256 threads.
#define MLP_BLOCKS  16
#define MLP_THREADS 256
#define MLP_SMEM_FLOATS (24576 + 4096 + 192 + 256 + 128 + 128)
#define MLP_SMEM_BYTES  (MLP_SMEM_FLOATS * 4)

__global__ __launch_bounds__(MLP_THREADS, 1)
void mlp_kernel(const float* __restrict__ params, float* __restrict__ out) {
    extern __shared__ float smem[];
    float* s_w1   = smem;                 // [192][128]
    float* s_w2   = s_w1 + 24576;         // [128][32]
    float* s_hist = s_w2 + 4096;          // [192]
    float* s_p1   = s_hist + 192;         // [2][128]
    float* s_h1   = s_p1 + 256;           // [128]
    float* s_l2   = s_h1 + 128;           // [4][32]

    const int tid = threadIdx.x;
    const int n   = blockIdx.x;

    #pragma unroll
    for (int i = tid; i < 24576 / 4; i += MLP_THREADS)
        reinterpret_cast<float4*>(s_w1)[i] = reinterpret_cast<const float4*>(params + P_W1)[i];
    #pragma unroll
    for (int i = tid; i < 4096 / 4; i += MLP_THREADS)
        reinterpret_cast<float4*>(s_w2)[i] = reinterpret_cast<const float4*>(params + P_W2)[i];

    cudaGridDependencySynchronize();

    if (tid < 192) {
        int c = tid >> 6;
        int b = tid & 63;
        const float* p = g_part + ((n * 3 + c) * BPS) * BINS + b;
        float s = 0.0f;
        #pragma unroll
        for (int k = 0; k < BPS; k++) s += p[k * BINS];
        s_hist[tid] = s;
    }
    __syncthreads();

    {
        const int j    = tid & 127;
        const int half = tid >> 7;
        const int c0   = half * 96;
        float acc = 0.0f;
        #pragma unroll 16
        for (int c = c0; c < c0 + 96; c++)
            acc = fmaf(s_hist[c], s_w1[c * 128 + j], acc);
        s_p1[half * 128 + j] = acc;
    }
    __syncthreads();
    if (tid < 128)
        s_h1[tid] = fmaxf(s_p1[tid] + s_p1[128 + tid] + params[P_B1 + tid], 0.0f);
    __syncthreads();

    if (tid < 128) {
        const int q = tid >> 5;
        const int k = tid & 31;
        float a = 0.0f;
        #pragma unroll
        for (int c = q * 32; c < q * 32 + 32; c++)
            a = fmaf(s_h1[c], s_w2[c * 32 + k], a);
        s_l2[tid] = a;
    }
    __syncthreads();

    if (tid < 32) {
        float a = params[P_B2 + tid] + params[P_G]
                + s_l2[tid] + s_l2[32 + tid] + s_l2[64 + tid] + s_l2[96 + tid];
        out[n * 32 + tid] = 1.0f / (1.0f + expf(-a));
    }
}

extern "C" void kernel_launch(void* const* d_in, const int* in_sizes, int n_in,
                              void* d_out, int out_size) {
    const float* img    = (const float*)d_in[0];
    const float* params = (const float*)d_in[1];
    float* out          = (float*)d_out;

    static bool attr_set = false;
    if (!attr_set) {
        cudaFuncSetAttribute(hist_kernel, cudaFuncAttributeMaxDynamicSharedMemorySize, HSMEM_BYTES);
        cudaFuncSetAttribute(mlp_kernel,  cudaFuncAttributeMaxDynamicSharedMemorySize, MLP_SMEM_BYTES);
        attr_set = true;
    }

    hist_kernel<<<NBLOCKS, HTHREADS, HSMEM_BYTES>>>(img);

    cudaLaunchConfig_t cfg = {};
    cfg.gridDim  = dim3(MLP_BLOCKS, 1, 1);
    cfg.blockDim = dim3(MLP_THREADS, 1, 1);
    cfg.dynamicSmemBytes = MLP_SMEM_BYTES;
    cudaLaunchAttribute attrs[1];
    attrs[0].id = cudaLaunchAttributeProgrammaticStreamSerialization;
    attrs[0].val.programmaticStreamSerializationAllowed = 1;
    cfg.attrs = attrs;
    cfg.numAttrs = 1;
    cudaLaunchKernelEx(&cfg, mlp_kernel, params, out);
}

// round 11
// speedup vs baseline: 1.2721x; 1.2721x over previous
#include <cuda_runtime.h>
#include <math.h>
#include <stdint.h>

// Problem constants
#define N_IMG     16
#define N_CH      3
#define NSLICE    (N_IMG * N_CH)          // 48
#define BINS      64
#define SLICE_ELEMS (1024 * 1024)

#define HTHREADS  128
#define BPS       9                               // 432 blocks (one wave at occ 3)
#define NBLOCKS   (NSLICE * BPS)
// Two u32 counter arrays [64][128] = 32 KB each
#define HSMEM_WORDS (2 * BINS * HTHREADS)
#define HSMEM_BYTES (HSMEM_WORDS * 4)             // 64 KB

// Params layout (in_ch,out_ch row-major), per reference
#define P_W1 0
#define P_B1 24576
#define P_W2 24704
#define P_B2 28800
#define P_G  28832

__device__ float g_part[NBLOCKS * BINS];

__global__ __launch_bounds__(HTHREADS, 3)
void hist_kernel(const float* __restrict__ img) {
    extern __shared__ unsigned int hh[];   // A = hh[0..8191], B = hh[8192..16383]
    const int tid = threadIdx.x;

    const int slice = blockIdx.x / BPS;
    const int chunk = blockIdx.x % BPS;
    const float4* base = reinterpret_cast<const float4*>(img + (size_t)slice * SLICE_ELEMS);
    const int n4   = SLICE_ELEMS / 4;                 // 262144
    const int per  = (n4 + BPS - 1) / BPS;            // 29128
    const int start = chunk * per;
    const int end   = min(start + per, n4);

    // ---- Prefetch FIRST batch before zeroing: loads fly during the prolog ----
    int i = start + tid;
    float4 A[8], B[8];
    bool hasA = (i + 7 * HTHREADS < end);
    if (hasA) {
        #pragma unroll
        for (int u = 0; u < 8; u++) A[u] = __ldcs(base + i + u * HTHREADS);
    }

    // zero both counter arrays (uint4 stores) while the LDGs are in flight
    {
        uint4* z = reinterpret_cast<uint4*>(hh);
        #pragma unroll
        for (int q = tid; q < HSMEM_WORDS / 4; q += HTHREADS)
            z[q] = make_uint4(0u, 0u, 0u, 0u);
    }
    __syncthreads();

    unsigned int* pA = hh + tid;                       // A[b][tid] at pA[b*128]
    unsigned int* pB = hh + BINS * HTHREADS + tid;     // B[b][tid] at pB[b*128]

    // Two independent RMW chains per pair; __fmul_rd keeps bin <= 63 for v in [0,1).
#define PROCPAIR(vA, vB) { \
        int ba = (int)__fmul_rd((vA), 64.0f); \
        int bb = (int)__fmul_rd((vB), 64.0f); \
        unsigned int ca = pA[ba * HTHREADS]; \
        unsigned int cb = pB[bb * HTHREADS]; \
        pA[ba * HTHREADS] = ca + 1u; \
        pB[bb * HTHREADS] = cb + 1u; }
#define PROC(v4) { PROCPAIR((v4).x, (v4).y); PROCPAIR((v4).z, (v4).w); }

    while (hasA) {
        const int j = i + 8 * HTHREADS;
        const bool hasB = (j + 7 * HTHREADS < end);
        if (hasB) {
            #pragma unroll
            for (int u = 0; u < 8; u++) B[u] = __ldcs(base + j + u * HTHREADS);
        }
        #pragma unroll
        for (int u = 0; u < 8; u++) PROC(A[u]);
        i = j;
        if (!hasB) break;
        const int k = j + 8 * HTHREADS;
        hasA = (k + 7 * HTHREADS < end);
        if (hasA) {
            #pragma unroll
            for (int u = 0; u < 8; u++) A[u] = __ldcs(base + k + u * HTHREADS);
        }
        #pragma unroll
        for (int u = 0; u < 8; u++) PROC(B[u]);
        i = k;
    }
    for (; i < end; i += HTHREADS) {
        float4 a = __ldcs(base + i);
        PROC(a);
    }
#undef PROC
#undef PROCPAIR
    __syncthreads();

    // Epilogue: warp w (of 4) reduces bins 16w..16w+15 over 128 columns x 2 arrays.
    const int wid  = tid >> 5;
    const int lane = tid & 31;
    #pragma unroll
    for (int r = 0; r < 16; r++) {
        const int b = wid * 16 + r;
        const unsigned int* ra = hh + b * HTHREADS;
        const unsigned int* rb = hh + BINS * HTHREADS + b * HTHREADS;
        unsigned int s = ra[lane] + ra[lane + 32] + ra[lane + 64] + ra[lane + 96]
                       + rb[lane] + rb[lane + 32] + rb[lane + 64] + rb[lane + 96];
        #pragma unroll
        for (int d = 16; d >= 1; d >>= 1)
            s += __shfl_down_sync(0xFFFFFFFFu, s, d);
        if (lane == 0)
            g_part[blockIdx.x * BINS + b] = (float)s;
    }
}

// MLP with PDL: grid=16 (one image per block), 256 threads.
#define MLP_BLOCKS  16
#define MLP_THREADS 256
#define MLP_SMEM_FLOATS (24576 + 4096 + 192 + 256 + 128 + 128)
#define MLP_SMEM_BYTES  (MLP_SMEM_FLOATS * 4)

__global__ __launch_bounds__(MLP_THREADS, 1)
void mlp_kernel(const float* __restrict__ params, float* __restrict__ out) {
    extern __shared__ float smem[];
    float* s_w1   = smem;                 // [192][128]
    float* s_w2   = s_w1 + 24576;         // [128][32]
    float* s_hist = s_w2 + 4096;          // [192]
    float* s_p1   = s_hist + 192;         // [2][128]
    float* s_h1   = s_p1 + 256;           // [128]
    float* s_l2   = s_h1 + 128;           // [4][32]

    const int tid = threadIdx.x;
    const int n   = blockIdx.x;

    // Pre-sync: stage weights (overlaps with hist via PDL)
    #pragma unroll
    for (int i = tid; i < 24576 / 4; i += MLP_THREADS)
        reinterpret_cast<float4*>(s_w1)[i] = reinterpret_cast<const float4*>(params + P_W1)[i];
    #pragma unroll
    for (int i = tid; i < 4096 / 4; i += MLP_THREADS)
        reinterpret_cast<float4*>(s_w2)[i] = reinterpret_cast<const float4*>(params + P_W2)[i];

    cudaGridDependencySynchronize();

    if (tid < 192) {
        int c = tid >> 6;
        int b = tid & 63;
        const float* p = g_part + ((n * 3 + c) * BPS) * BINS + b;
        float s = 0.0f;
        #pragma unroll
        for (int k = 0; k < BPS; k++) s += p[k * BINS];
        s_hist[tid] = s;
    }
    __syncthreads();

    {
        const int j    = tid & 127;
        const int half = tid >> 7;
        const int c0   = half * 96;
        float acc = 0.0f;
        #pragma unroll 16
        for (int c = c0; c < c0 + 96; c++)
            acc = fmaf(s_hist[c], s_w1[c * 128 + j], acc);
        s_p1[half * 128 + j] = acc;
    }
    __syncthreads();
    if (tid < 128)
        s_h1[tid] = fmaxf(s_p1[tid] + s_p1[128 + tid] + params[P_B1 + tid], 0.0f);
    __syncthreads();

    if (tid < 128) {
        const int q = tid >> 5;
        const int k = tid & 31;
        float a = 0.0f;
        #pragma unroll
        for (int c = q * 32; c < q * 32 + 32; c++)
            a = fmaf(s_h1[c], s_w2[c * 32 + k], a);
        s_l2[tid] = a;
    }
    __syncthreads();

    if (tid < 32) {
        float a = params[P_B2 + tid] + params[P_G]
                + s_l2[tid] + s_l2[32 + tid] + s_l2[64 + tid] + s_l2[96 + tid];
        out[n * 32 + tid] = 1.0f / (1.0f + expf(-a));
    }
}

extern "C" void kernel_launch(void* const* d_in, const int* in_sizes, int n_in,
                              void* d_out, int out_size) {
    const float* img    = (const float*)d_in[0];
    const float* params = (const float*)d_in[1];
    float* out          = (float*)d_out;

    static bool attr_set = false;
    if (!attr_set) {
        cudaFuncSetAttribute(hist_kernel, cudaFuncAttributeMaxDynamicSharedMemorySize, HSMEM_BYTES);
        cudaFuncSetAttribute(mlp_kernel,  cudaFuncAttributeMaxDynamicSharedMemorySize, MLP_SMEM_BYTES);
        attr_set = true;
    }

    hist_kernel<<<NBLOCKS, HTHREADS, HSMEM_BYTES>>>(img);

    cudaLaunchConfig_t cfg = {};
    cfg.gridDim  = dim3(MLP_BLOCKS, 1, 1);
    cfg.blockDim = dim3(MLP_THREADS, 1, 1);
    cfg.dynamicSmemBytes = MLP_SMEM_BYTES;
    cudaLaunchAttribute attrs[1];
    attrs[0].id = cudaLaunchAttributeProgrammaticStreamSerialization;
    attrs[0].val.programmaticStreamSerializationAllowed = 1;
    cfg.attrs = attrs;
    cfg.numAttrs = 1;
    cudaLaunchKernelEx(&cfg, mlp_kernel, params, out);
}